// round 2
// baseline (speedup 1.0000x reference)
#include <cuda_runtime.h>
#include <cstdint>

// Problem constants
#define BB      4
#define NN      2048
#define NG      512            // N/4 groups per batch
#define GROUPS  2048           // BB * NG
#define MM      64             // G1*G2 grid cells
#define CC      128            // channels
#define TOK     8192           // MM*CC floats per token
#define RK      8
#define RRR     512            // RK^3
#define SPITCH  129            // smem pitch for s tile (conflict-free)
#define MASKN   524288         // B*N*M mask elements

// Scratch (allocation-free rule: __device__ globals)
__device__ float g_s[(size_t)GROUPS * TOK];   // 64 MB group sums
__device__ float g_z[(size_t)GROUPS * RRR];   // 4 MB  projected ranks
__device__ float g_y[(size_t)GROUPS * RRR];   // 4 MB  core output ranks
__device__ int   g_maskmode;                  // 0=int32, 1=uint8/bool, 2=float32

// ---------------------------------------------------------------------------
// Kernel 0: detect mask dtype. Scans the first MASKN bytes (safe minimum size
// for all candidate dtypes). 1 block, 1024 threads.
//   float32: 1.0f bytes = {00,00,80,3F} -> bytes >= 2 present      -> mode 2
//   uint8  : values {0,1} at every byte offset (25% density)       -> mode 1
//   int32  : values {0,1} only at byte offset %4 == 0              -> mode 0
// ---------------------------------------------------------------------------
__global__ void __launch_bounds__(1024) k0_detect_mask(const unsigned char* __restrict__ mask)
{
    __shared__ int s_ge2, s_odd;
    if (threadIdx.x == 0) { s_ge2 = 0; s_odd = 0; }
    __syncthreads();
    const uint4* p = (const uint4*)mask;
    unsigned acc = 0;
    for (int i = threadIdx.x; i < MASKN / 16; i += 1024) {
        uint4 v = p[i];
        acc |= (v.x | v.y | v.z | v.w);
        // fold the "odd-byte" info: bytes 1..3 of each little-endian word
    }
    int ge2 = (acc & 0xFEFEFEFEu) ? 1 : 0;   // any byte with value >= 2
    int odd = (acc & 0xFFFFFF00u) ? 1 : 0;   // any nonzero byte at offset%4 != 0
    if (ge2) atomicOr(&s_ge2, 1);
    if (odd) atomicOr(&s_odd, 1);
    __syncthreads();
    if (threadIdx.x == 0)
        g_maskmode = s_ge2 ? 2 : (s_odd ? 1 : 0);
}

// ---------------------------------------------------------------------------
// Kernel 1: per group (b,g): s = sum of 4 tokens; z = in-factor projection.
// grid = 2048 blocks, 256 threads.
// ---------------------------------------------------------------------------
__global__ void __launch_bounds__(256) k1_reduce_project(
    const float* __restrict__ x,
    const float* __restrict__ in_f0,   // (8,8)
    const float* __restrict__ in_f1,   // (8,8)
    const float* __restrict__ in_f2)   // (128,8)
{
    __shared__ float s[MM * SPITCH];   // s[m][e], pitch 129
    __shared__ float f2s[CC * RK];     // in_f2 as stored: [e][F]
    __shared__ float f0s[64], f1s[64];
    __shared__ float t1[MM * 9];       // t1[m][F], pitch 9
    __shared__ float t2[RRR];          // t2[a][E][F]

    const int tid = threadIdx.x;
    const size_t gidx = blockIdx.x;

    if (tid < 64) { f0s[tid] = in_f0[tid]; f1s[tid] = in_f1[tid]; }
    #pragma unroll
    for (int i = tid; i < CC * RK; i += 256) f2s[i] = in_f2[i];

    // ---- phase 1: sum 4 tokens (vectorized), write smem + global scratch ----
    const float4* xb = (const float4*)(x + gidx * (size_t)(4 * TOK));
    float4*       sg = (float4*)(g_s + gidx * (size_t)TOK);
    #pragma unroll
    for (int it = 0; it < 8; it++) {
        int i = tid + it * 256;                 // float4 index within token
        float4 v0 = xb[i];
        float4 v1 = xb[i + 2048];
        float4 v2 = xb[i + 4096];
        float4 v3 = xb[i + 6144];
        float4 r;
        r.x = (v0.x + v1.x) + (v2.x + v3.x);
        r.y = (v0.y + v1.y) + (v2.y + v3.y);
        r.z = (v0.z + v1.z) + (v2.z + v3.z);
        r.w = (v0.w + v1.w) + (v2.w + v3.w);
        sg[i] = r;
        int m = i >> 5;                         // (i*4)/128
        int e = (i & 31) << 2;
        float* sp = &s[m * SPITCH + e];
        sp[0] = r.x; sp[1] = r.y; sp[2] = r.z; sp[3] = r.w;
    }
    __syncthreads();

    // ---- t1[m][F] = sum_e s[m][e] * in_f2[e][F] ----
    {
        int m  = tid & 63;
        int F0 = (tid >> 6) << 1;
        float acc0 = 0.f, acc1 = 0.f;
        const float* srow = &s[m * SPITCH];
        #pragma unroll 8
        for (int e = 0; e < CC; e++) {
            float sv = srow[e];
            acc0 += sv * f2s[e * RK + F0];
            acc1 += sv * f2s[e * RK + F0 + 1];
        }
        t1[m * 9 + F0]     = acc0;
        t1[m * 9 + F0 + 1] = acc1;
    }
    __syncthreads();

    // ---- t2[a][E][F] = sum_d t1[a*8+d][F] * in_f1[d][E] ----
    #pragma unroll
    for (int o = tid; o < RRR; o += 256) {
        int a = o >> 6, E = (o >> 3) & 7, F = o & 7;
        float acc = 0.f;
        #pragma unroll
        for (int d = 0; d < 8; d++)
            acc += t1[(a * 8 + d) * 9 + F] * f1s[d * 8 + E];
        t2[o] = acc;
    }
    __syncthreads();

    // ---- z[D][E][F] = sum_a t2[a][E][F] * in_f0[a][D] ----
    float* zg = g_z + gidx * (size_t)RRR;
    #pragma unroll
    for (int o = tid; o < RRR; o += 256) {
        int D = o >> 6, EF = o & 63;
        float acc = 0.f;
        #pragma unroll
        for (int a = 0; a < 8; a++)
            acc += t2[a * 64 + EF] * f0s[a * 8 + D];
        zg[o] = acc;
    }
}

// ---------------------------------------------------------------------------
// Kernel 2: Y = Z @ core^T   (2048 x 512) @ (512 x 512)^T, fp32 SIMT tiles.
// grid = (32, 8), 256 threads. BM=BN=64, BK=16, 4x4 register tile.
// ---------------------------------------------------------------------------
__global__ void __launch_bounds__(256) k2_core_gemm(
    const float* __restrict__ W)       // core, (512 out-ranks) x (512 in-ranks)
{
    __shared__ float As[16][68];       // As[k][m]
    __shared__ float Bs[16][68];       // Bs[k][n]

    const int tid = threadIdx.x;
    const int bm = blockIdx.x * 64;
    const int bn = blockIdx.y * 64;
    const int tx = tid & 15, ty = tid >> 4;
    const int lr = tid >> 2;           // 0..63: row within tile
    const int lk = (tid & 3) << 2;     // 0,4,8,12: k offset

    float acc[4][4];
    #pragma unroll
    for (int i = 0; i < 4; i++)
        #pragma unroll
        for (int j = 0; j < 4; j++) acc[i][j] = 0.f;

    const float* Z = g_z;
    for (int k0 = 0; k0 < RRR; k0 += 16) {
        float4 av = *(const float4*)(Z + (size_t)(bm + lr) * RRR + k0 + lk);
        float4 bv = *(const float4*)(W + (size_t)(bn + lr) * RRR + k0 + lk);
        __syncthreads();
        As[lk + 0][lr] = av.x; As[lk + 1][lr] = av.y;
        As[lk + 2][lr] = av.z; As[lk + 3][lr] = av.w;
        Bs[lk + 0][lr] = bv.x; Bs[lk + 1][lr] = bv.y;
        Bs[lk + 2][lr] = bv.z; Bs[lk + 3][lr] = bv.w;
        __syncthreads();
        #pragma unroll
        for (int k = 0; k < 16; k++) {
            float a[4], b[4];
            #pragma unroll
            for (int i = 0; i < 4; i++) a[i] = As[k][ty * 4 + i];
            #pragma unroll
            for (int j = 0; j < 4; j++) b[j] = Bs[k][tx * 4 + j];
            #pragma unroll
            for (int i = 0; i < 4; i++)
                #pragma unroll
                for (int j = 0; j < 4; j++) acc[i][j] += a[i] * b[j];
        }
    }
    #pragma unroll
    for (int i = 0; i < 4; i++)
        #pragma unroll
        for (int j = 0; j < 4; j++)
            g_y[(size_t)(bm + ty * 4 + i) * RRR + bn + tx * 4 + j] = acc[i][j];
}

// ---------------------------------------------------------------------------
// Kernel 3: per group: expand ranks -> h, out = (h + s) * invw(mask).
// grid = 2048 blocks, 256 threads.
// ---------------------------------------------------------------------------
__global__ void __launch_bounds__(256) k3_expand(
    const float* __restrict__ out_f0,  // (8,8)
    const float* __restrict__ out_f1,  // (8,8)
    const float* __restrict__ out_f2,  // (128,8)
    const void*  __restrict__ maskp,
    float* __restrict__ out)
{
    __shared__ float ys[RRR];          // y[A][B][C]
    __shared__ float u1[RRR];          // [o][B][C]
    __shared__ float u2[RRR];          // [m][C]  (m = o*8+p)
    __shared__ float f0s[64], f1s[64];
    __shared__ float f2t[RK * CC];     // transposed: f2t[C][q]
    __shared__ float invw[MM];

    const int tid = threadIdx.x;
    const size_t gidx = blockIdx.x;

    const float* yg = g_y + gidx * (size_t)RRR;
    #pragma unroll
    for (int i = tid; i < RRR; i += 256) ys[i] = yg[i];
    if (tid < 64) { f0s[tid] = out_f0[tid]; f1s[tid] = out_f1[tid]; }
    #pragma unroll
    for (int i = tid; i < RK * CC; i += 256) {
        int q = i >> 3, Cr = i & 7;
        f2t[Cr * CC + q] = out_f2[i];
    }
    if (tid < 64) {
        int mode = g_maskmode;
        int w;
        if (mode == 1) {
            const unsigned char* mb = (const unsigned char*)maskp + gidx * (size_t)256;
            w = (mb[tid]       ? 0 : 1) + (mb[tid + 64]  ? 0 : 1)
              + (mb[tid + 128] ? 0 : 1) + (mb[tid + 192] ? 0 : 1);
        } else if (mode == 0) {
            const int* mi = (const int*)maskp + gidx * (size_t)256;
            w = (mi[tid]       ? 0 : 1) + (mi[tid + 64]  ? 0 : 1)
              + (mi[tid + 128] ? 0 : 1) + (mi[tid + 192] ? 0 : 1);
        } else {
            const float* mf = (const float*)maskp + gidx * (size_t)256;
            w = (mf[tid]       != 0.f ? 0 : 1) + (mf[tid + 64]  != 0.f ? 0 : 1)
              + (mf[tid + 128] != 0.f ? 0 : 1) + (mf[tid + 192] != 0.f ? 0 : 1);
        }
        invw[tid] = (w > 0) ? 1.0f / ((float)w + 1e-10f) : 0.0f;
    }
    __syncthreads();

    // u1[o][B][C] = sum_A y[A][B][C] * out_f0[o][A]
    #pragma unroll
    for (int o = tid; o < RRR; o += 256) {
        int oo = o >> 6, BC = o & 63;
        float acc = 0.f;
        #pragma unroll
        for (int A = 0; A < 8; A++)
            acc += ys[A * 64 + BC] * f0s[oo * 8 + A];
        u1[o] = acc;
    }
    __syncthreads();

    // u2[m][C] = sum_B u1[o][B][C] * out_f1[p][B]   (m = o*8+p)
    #pragma unroll
    for (int o = tid; o < RRR; o += 256) {
        int oo = o >> 6, p = (o >> 3) & 7, Cr = o & 7;
        float acc = 0.f;
        #pragma unroll
        for (int Bx = 0; Bx < 8; Bx++)
            acc += u1[oo * 64 + Bx * 8 + Cr] * f1s[p * 8 + Bx];
        u2[o] = acc;   // index == m*8 + Cr
    }
    __syncthreads();

    // out[m][q] = (sum_C u2[m][C]*out_f2[q][C] + s[m][q]) * invw[m]
    const float4* sg = (const float4*)(g_s + gidx * (size_t)TOK);
    float4*       og = (float4*)(out + gidx * (size_t)TOK);
    #pragma unroll
    for (int it = 0; it < 8; it++) {
        int i = tid + it * 256;
        int m  = i >> 5;
        int q0 = (i & 31) << 2;
        float4 sv = sg[i];
        float r0 = 0.f, r1 = 0.f, r2 = 0.f, r3 = 0.f;
        #pragma unroll
        for (int Cr = 0; Cr < 8; Cr++) {
            float u = u2[m * 8 + Cr];                       // warp-uniform broadcast
            float4 f = *(const float4*)&f2t[Cr * CC + q0];  // conflict-free
            r0 += u * f.x; r1 += u * f.y; r2 += u * f.z; r3 += u * f.w;
        }
        float iw = invw[m];
        float4 ov;
        ov.x = (r0 + sv.x) * iw;
        ov.y = (r1 + sv.y) * iw;
        ov.z = (r2 + sv.z) * iw;
        ov.w = (r3 + sv.w) * iw;
        og[i] = ov;
    }
}

// ---------------------------------------------------------------------------
// Launch: inputs per metadata order:
// 0:x 1:core 2:out_f0 3:out_f1 4:out_f2 5:in_f0 6:in_f1 7:in_f2 8:mask
// ---------------------------------------------------------------------------
extern "C" void kernel_launch(void* const* d_in, const int* in_sizes, int n_in,
                              void* d_out, int out_size)
{
    const float* x      = (const float*)d_in[0];
    const float* core   = (const float*)d_in[1];
    const float* out_f0 = (const float*)d_in[2];
    const float* out_f1 = (const float*)d_in[3];
    const float* out_f2 = (const float*)d_in[4];
    const float* in_f0  = (const float*)d_in[5];
    const float* in_f1  = (const float*)d_in[6];
    const float* in_f2  = (const float*)d_in[7];
    float* out = (float*)d_out;

    k0_detect_mask<<<1, 1024>>>((const unsigned char*)d_in[8]);
    k1_reduce_project<<<GROUPS, 256>>>(x, in_f0, in_f1, in_f2);
    dim3 g2(GROUPS / 64, RRR / 64);
    k2_core_gemm<<<g2, 256>>>(core);
    k3_expand<<<GROUPS, 256>>>(out_f0, out_f1, out_f2, d_in[8], out);
}